// round 11
// baseline (speedup 1.0000x reference)
#include <cuda_runtime.h>

#define BB 64
#define TT 512
#define II 512
#define HH 1024

#define NBLK 128
#define NTHR 256

// [g][t][b][h] input-side gate pre-activations (402 MB)
__device__ float g_xg[(size_t)3 * TT * BB * HH];
// double-buffered hidden state
__device__ float g_h[2][BB * HH];
// grid barrier state
__device__ unsigned g_bar;
__device__ unsigned g_gen;

__device__ __forceinline__ void gridbar(unsigned& gen) {
    __syncthreads();
    gen++;
    if (threadIdx.x == 0) {
        __threadfence();
        unsigned arr = atomicAdd(&g_bar, 1u);
        if (arr == NBLK - 1) {
            g_bar = 0;
            __threadfence();
            atomicExch(&g_gen, gen);
        } else {
            volatile unsigned* vg = &g_gen;
            while (*vg < gen) { }
            __threadfence();
        }
    }
    __syncthreads();
}

__device__ __forceinline__ void cp_async16(void* smem_dst, const void* gsrc) {
    unsigned s = (unsigned)__cvta_generic_to_shared(smem_dst);
    asm volatile("cp.async.cg.shared.global [%0], [%1], 16;\n" :: "r"(s), "l"(gsrc));
}
#define CP_COMMIT() asm volatile("cp.async.commit_group;\n" ::: "memory")
#define CP_WAIT(n)  asm volatile("cp.async.wait_group %0;\n" :: "n"(n) : "memory")

#define FMA2(d, a, b) asm("fma.rn.f32x2 %0, %1, %2, %0;" : "+l"(d) : "l"(a), "l"(b))
#define DUP2(d, s)    asm("mov.b64 %0, {%1, %1};" : "=l"(d) : "r"(__float_as_uint(s)))

// ---------------------------------------------------------------------------
// Phase 1: Xg[t][b][h] = x[b][t][:] . Wg[h][:] + bias_g[h]   (3 gates)
// Block tile 128m x 64n, 256 threads, thread tile 8m x 4n, Kc = 16.
// v3: inner product uses packed fma.rn.f32x2 over n-pairs (16 FFMA2 + 8 DUP
// per k instead of 32 FFMA) -> FMA-pipe time per k-iter halves.
// ---------------------------------------------------------------------------
__global__ __launch_bounds__(256, 2) void gemm_in(
    const float* __restrict__ x,
    const float* __restrict__ W0, const float* __restrict__ W1, const float* __restrict__ W2,
    const float* __restrict__ c0, const float* __restrict__ c1, const float* __restrict__ c2)
{
    __shared__ float As[16][128];
    __shared__ float Bs[16][64];
    const int g = blockIdx.z;
    const float* W    = (g == 0) ? W0 : (g == 1) ? W1 : W2;
    const float* bias = (g == 0) ? c0 : (g == 1) ? c1 : c2;
    const int m0 = blockIdx.y * 128;
    const int n0 = blockIdx.x * 64;
    const int tid = threadIdx.x;
    const int n_thr = tid & 15;
    const int m_thr = tid >> 4;
    const int ar = tid >> 1, ak = (tid & 1) * 8;
    const int brow = tid >> 2, bk = (tid & 3) * 4;

    unsigned long long acc2[8][2];
#pragma unroll
    for (int i = 0; i < 8; i++) { acc2[i][0] = 0ull; acc2[i][1] = 0ull; }

    for (int k0 = 0; k0 < II; k0 += 16) {
        float4 a0 = *(const float4*)&x[(size_t)(m0 + ar) * II + k0 + ak];
        float4 a1 = *(const float4*)&x[(size_t)(m0 + ar) * II + k0 + ak + 4];
        float4 bv = *(const float4*)&W[(size_t)(n0 + brow) * II + k0 + bk];
        As[ak + 0][ar] = a0.x; As[ak + 1][ar] = a0.y; As[ak + 2][ar] = a0.z; As[ak + 3][ar] = a0.w;
        As[ak + 4][ar] = a1.x; As[ak + 5][ar] = a1.y; As[ak + 6][ar] = a1.z; As[ak + 7][ar] = a1.w;
        Bs[bk + 0][brow] = bv.x; Bs[bk + 1][brow] = bv.y; Bs[bk + 2][brow] = bv.z; Bs[bk + 3][brow] = bv.w;
        __syncthreads();
#pragma unroll
        for (int k = 0; k < 16; k++) {
            float a[8];
            *(float4*)&a[0] = *(const float4*)&As[k][m_thr * 8];
            *(float4*)&a[4] = *(const float4*)&As[k][m_thr * 8 + 4];
            union { float4 f; unsigned long long u[2]; } bb;
            bb.f = *(const float4*)&Bs[k][n_thr * 4];
#pragma unroll
            for (int i = 0; i < 8; i++) {
                unsigned long long a2;
                DUP2(a2, a[i]);
                FMA2(acc2[i][0], a2, bb.u[0]);
                FMA2(acc2[i][1], a2, bb.u[1]);
            }
        }
        __syncthreads();
    }

    float4 bs4 = *(const float4*)&bias[n0 + n_thr * 4];
#pragma unroll
    for (int i = 0; i < 8; i++) {
        int m = m0 + m_thr * 8 + i;
        int b = m >> 9;      // m = b*T + t, T = 512
        int t = m & 511;
        union { unsigned long long u; float f[2]; } lo, hi;
        lo.u = acc2[i][0]; hi.u = acc2[i][1];
        float4 o;
        o.x = lo.f[0] + bs4.x; o.y = lo.f[1] + bs4.y;
        o.z = hi.f[0] + bs4.z; o.w = hi.f[1] + bs4.w;
        *(float4*)&g_xg[(((size_t)g * TT + t) * BB + b) * HH + n0 + n_thr * 4] = o;
    }
}

// ---------------------------------------------------------------------------
// Phase 2 v3: persistent kernel; weights in registers; 2 h-cols per thread.
// 128 blocks x 256 threads (8 warps). Block: 8 h-cols x 3 gates x 64 batches.
// Warp w owns k-slice [w*128, w*128+128). Lane = hp*8 + ksub:
//   hp   in 0..3 -> h-col pair (h0+2hp, h0+2hp+1)
//   ksub in 0..7 -> k offsets ksub*4 + j*32, j=0..3 (16 k-floats/thread)
// 96 weight floats/thread (2h x 3g x 16k) as 48 packed b64 pairs.
// Per (thread, batch): 4 LDS.128 + 48 FFMA2 -> every h-load feeds 6 accums
// (half the LDS-per-MAC of v2). Epilogue xg/h operands prefetched at step top.
// ---------------------------------------------------------------------------
__global__ __launch_bounds__(NTHR, 1) void gru_steps(
    const float* __restrict__ Whr, const float* __restrict__ Whi, const float* __restrict__ Whn,
    float* __restrict__ out, int write_hlast)
{
    extern __shared__ float smem[];
    float* hbuf = smem;                    // [2][8][1024] = 16384 floats (64 KB)
    float* red  = smem + 2 * 8 * HH;       // [8w][64b][8h][3g] = 12288 floats (48 KB)

    const int tid  = threadIdx.x;
    const int warp = tid >> 5;             // 0..7 : k-slice
    const int lane = tid & 31;
    const int hp   = lane >> 3;            // 0..3 : h-col pair
    const int ksub = lane & 7;             // 0..7 : 4-float subrange
    const int ht = blockIdx.x;
    const int h0 = ht * 8;
    const int kbase = warp * 128 + ksub * 4;

    // ---- Load weights into registers (persist across all 512 steps). ----
    // wA = h-col h0+2hp, wB = h-col h0+2hp+1. Pair index j*2+p covers
    // k = kbase + j*32 + p*2 .. +1.
    unsigned long long wAr[8], wAi[8], wAn[8], wBr[8], wBi[8], wBn[8];
    {
        const size_t rowA = (size_t)(h0 + hp * 2) * HH + kbase;
        const size_t rowB = rowA + HH;
#pragma unroll
        for (int j = 0; j < 4; j++) {
#pragma unroll
            for (int p = 0; p < 2; p++) {
                const size_t o = j * 32 + p * 2;
                wAr[j * 2 + p] = *(const unsigned long long*)&Whr[rowA + o];
                wAi[j * 2 + p] = *(const unsigned long long*)&Whi[rowA + o];
                wAn[j * 2 + p] = *(const unsigned long long*)&Whn[rowA + o];
                wBr[j * 2 + p] = *(const unsigned long long*)&Whr[rowB + o];
                wBi[j * 2 + p] = *(const unsigned long long*)&Whi[rowB + o];
                wBn[j * 2 + p] = *(const unsigned long long*)&Whn[rowB + o];
            }
        }
    }

    // Zero h[0] (this block's 512-float slice).
    {
        float* hz = &g_h[0][0];
        for (int i = tid; i < 512; i += NTHR) hz[ht * 512 + i] = 0.f;
    }

    unsigned gen = *(volatile unsigned*)&g_gen;
    gridbar(gen);

    // Epilogue output assignment: thread handles o = tid and o = tid + 256.
    const int b_o0 = tid >> 3,        hh_o0 = tid & 7;
    const int b_o1 = (tid + 256) >> 3, hh_o1 = (tid + 256) & 7;
    const size_t ix0 = (size_t)b_o0 * HH + h0 + hh_o0;
    const size_t ix1 = (size_t)b_o1 * HH + h0 + hh_o1;

    for (int t = 0; t < TT; t++) {
        const float* hcur = g_h[t & 1];
        float* hnxt = g_h[(t & 1) ^ 1];

        // ---- Prefetch epilogue operands (independent of recurrence). ----
        const size_t xoff = (size_t)t * BB * HH;
        const float* xr_p = g_xg + xoff;
        const float* xi_p = g_xg + (size_t)TT * BB * HH + xoff;
        const float* xn_p = g_xg + 2 * (size_t)TT * BB * HH + xoff;
        float xr0 = xr_p[ix0], xi0 = xi_p[ix0], xn0 = xn_p[ix0];
        float xr1 = xr_p[ix1], xi1 = xi_p[ix1], xn1 = xn_p[ix1];
        float hp0 = __ldcg(&hcur[ix0]);
        float hp1 = __ldcg(&hcur[ix1]);

        // Stage chunk 0 (batches 0..7): straight 32KB copy, L1-bypassed.
        {
            const float* src = hcur;
            float* dst = hbuf;
#pragma unroll
            for (int i = 0; i < 8; i++) {
                int idx = (tid + i * NTHR) * 4;
                cp_async16(dst + idx, src + idx);
            }
            CP_COMMIT();
        }

        for (int c = 0; c < 8; c++) {
            if (c < 7) {
                __syncthreads();             // WAR: target buf fully consumed
                const float* src = hcur + (c + 1) * 8 * HH;
                float* dst = hbuf + ((c + 1) & 1) * (8 * HH);
#pragma unroll
                for (int i = 0; i < 8; i++) {
                    int idx = (tid + i * NTHR) * 4;
                    cp_async16(dst + idx, src + idx);
                }
                CP_COMMIT();
                CP_WAIT(1);                  // chunk c arrived
            } else {
                CP_WAIT(0);
            }
            __syncthreads();                 // chunk c visible to all warps

            const float* hc = hbuf + (c & 1) * (8 * HH) + kbase;
#pragma unroll
            for (int bb = 0; bb < 8; bb++) {
                const int b = c * 8 + bb;
                unsigned long long aAr = 0, aAi = 0, aAn = 0;
                unsigned long long aBr = 0, aBi = 0, aBn = 0;
                const float* hrow = hc + bb * HH;
#pragma unroll
                for (int j = 0; j < 4; j++) {
                    union { float4 f; unsigned long long u[2]; } hv;
                    hv.f = *(const float4*)(hrow + j * 32);
                    FMA2(aAr, wAr[j * 2 + 0], hv.u[0]);
                    FMA2(aAi, wAi[j * 2 + 0], hv.u[0]);
                    FMA2(aAn, wAn[j * 2 + 0], hv.u[0]);
                    FMA2(aBr, wBr[j * 2 + 0], hv.u[0]);
                    FMA2(aBi, wBi[j * 2 + 0], hv.u[0]);
                    FMA2(aBn, wBn[j * 2 + 0], hv.u[0]);
                    FMA2(aAr, wAr[j * 2 + 1], hv.u[1]);
                    FMA2(aAi, wAi[j * 2 + 1], hv.u[1]);
                    FMA2(aAn, wAn[j * 2 + 1], hv.u[1]);
                    FMA2(aBr, wBr[j * 2 + 1], hv.u[1]);
                    FMA2(aBi, wBi[j * 2 + 1], hv.u[1]);
                    FMA2(aBn, wBn[j * 2 + 1], hv.u[1]);
                }
                union { unsigned long long u; float f[2]; } u0, u1, u2, u3, u4, u5;
                u0.u = aAr; u1.u = aAi; u2.u = aAn;
                u3.u = aBr; u4.u = aBi; u5.u = aBn;
                float sAr = u0.f[0] + u0.f[1];
                float sAi = u1.f[0] + u1.f[1];
                float sAn = u2.f[0] + u2.f[1];
                float sBr = u3.f[0] + u3.f[1];
                float sBi = u4.f[0] + u4.f[1];
                float sBn = u5.f[0] + u5.f[1];
                // reduce over 8 ksub lanes (xor 1,2,4 within each octet)
#pragma unroll
                for (int m = 1; m <= 4; m <<= 1) {
                    sAr += __shfl_xor_sync(0xFFFFFFFFu, sAr, m);
                    sAi += __shfl_xor_sync(0xFFFFFFFFu, sAi, m);
                    sAn += __shfl_xor_sync(0xFFFFFFFFu, sAn, m);
                    sBr += __shfl_xor_sync(0xFFFFFFFFu, sBr, m);
                    sBi += __shfl_xor_sync(0xFFFFFFFFu, sBi, m);
                    sBn += __shfl_xor_sync(0xFFFFFFFFu, sBn, m);
                }
                if (ksub == 0) {
                    float* rp = &red[(((warp * 64) + b) * 8 + hp * 2) * 3];
                    rp[0] = sAr; rp[1] = sAi; rp[2] = sAn;
                    rp[3] = sBr; rp[4] = sBi; rp[5] = sBn;
                }
            }
        }

        __syncthreads();   // red[] complete

        // ---- Block reduce over 8 warp k-slices + gate epilogue (2 outs). ----
#pragma unroll
        for (int q = 0; q < 2; q++) {
            const int b  = q ? b_o1 : b_o0;
            const int hh = q ? hh_o1 : hh_o0;
            const size_t ix = q ? ix1 : ix0;
            const float xr = q ? xr1 : xr0;
            const float xi = q ? xi1 : xi0;
            const float xn = q ? xn1 : xn0;
            const float hpv = q ? hp1 : hp0;
            float sr = 0.f, si = 0.f, sn = 0.f;
#pragma unroll
            for (int w = 0; w < 8; w++) {
                const float* rp = &red[(((w * 64) + b) * 8 + hh) * 3];
                sr += rp[0]; si += rp[1]; sn += rp[2];
            }
            float rg = __fdividef(1.f, 1.f + __expf(-(xr + sr)));
            float ig = __fdividef(1.f, 1.f + __expf(-(xi + si)));
            float zi = xn + rg * sn;
            float ng = 1.f - __fdividef(2.f, __expf(2.f * zi) + 1.f);   // tanh(zi)
            float hn = (1.f - ig) * ng + ig * hpv;
            hnxt[ix] = hn;
            out[((size_t)b * TT + t) * HH + h0 + hh] = hn;
            if (write_hlast && t == TT - 1)
                out[(size_t)BB * TT * HH + ix] = hn;
        }

        if (t < TT - 1) gridbar(gen);
    }
}

extern "C" void kernel_launch(void* const* d_in, const int* in_sizes, int n_in,
                              void* d_out, int out_size) {
    const float* x   = (const float*)d_in[0];
    const float* Wir = (const float*)d_in[1];
    const float* Wii = (const float*)d_in[2];
    const float* Win = (const float*)d_in[3];
    const float* bir = (const float*)d_in[4];
    const float* bii = (const float*)d_in[5];
    const float* bin = (const float*)d_in[6];
    const float* Whr = (const float*)d_in[7];
    const float* Whi = (const float*)d_in[8];
    const float* Whn = (const float*)d_in[9];
    float* out = (float*)d_out;

    // Phase 1: input-side projections for all 3 gates.
    dim3 g1(HH / 64, (BB * TT) / 128, 3);
    gemm_in<<<g1, 256>>>(x, Wir, Wii, Win, bir, bii, bin);

    // Phase 2: persistent recurrence kernel.
    const int smem_bytes = (2 * 8 * HH + 8 * 64 * 8 * 3) * (int)sizeof(float);  // 114688
    cudaFuncSetAttribute(gru_steps, cudaFuncAttributeMaxDynamicSharedMemorySize, smem_bytes);
    int write_hlast = (out_size >= BB * TT * HH + BB * HH) ? 1 : 0;
    gru_steps<<<NBLK, NTHR, smem_bytes>>>(Whr, Whi, Whn, out, write_hlast);
}